// round 10
// baseline (speedup 1.0000x reference)
#include <cuda_runtime.h>
#include <cuda_bf16.h>
#include <cstdint>

// Problem constants (fixed by the dataset)
#define BB  16
#define TT  128   // txt_T
#define MM  512   // mel_T
#define NC  80    // N_MEL

// k_logprob tiling (exact round-4 proven shape)
#define TBLK 32
#define MBLK 128
#define K1_THREADS 128

// fused scan: 8 iterations x (4 groups x 16 steps)
#define NIT 8
#define CSF 16

// Scratch (no cudaMalloc allowed). Pad: scan E-stage reads row m=512.
__device__ __align__(16) float g_elp[(size_t)BB * MM * TT + 4096]; // exp(lp), [b][m][t]
__device__ float g_alpha[BB];
__device__ unsigned g_cnt = 0;

// smem layout (bytes) for k_logprob (round-4)
#define SM_X2_OFF 0
#define SM_X_OFF  (NC * 64 * 8)                 // 40960
#define SM_WA_OFF (SM_X_OFF + NC * 64 * 8)      // 81920
#define SM_KP_OFF (SM_WA_OFF + TBLK * NC * 8)   // 102400
#define SM_KC_OFF (SM_KP_OFF + TBLK * 4 * 4)    // 102912
#define SM_TOTAL  (SM_KC_OFF + TBLK * 4)        // 103040

// dynamic smem for k_scanf (floats):
//   EB [2][64][128] = 16384, BS [4][17][128] = 8704, QS [2][128] = 256,
//   WR [16], WM [4]
#define SMEM_SCANF ((2*64*128 + 4*17*128 + 2*128 + 16 + 4) * 4)

// ---- packed f32x2 helpers (sm_103a dual-fp32 pipe; PTX-only) ----
__device__ __forceinline__ void fma2(unsigned long long& d,
                                     unsigned long long a,
                                     unsigned long long b) {
    asm("fma.rn.f32x2 %0, %1, %2, %0;" : "+l"(d) : "l"(a), "l"(b));
}
__device__ __forceinline__ unsigned long long pack2(float lo, float hi) {
    unsigned long long r;
    asm("mov.b64 %0, {%1, %2};" : "=l"(r) : "f"(lo), "f"(hi));
    return r;
}
__device__ __forceinline__ float2 unpack2(unsigned long long v) {
    float lo, hi;
    asm("mov.b64 {%0, %1}, %2;" : "=f"(lo), "=f"(hi) : "l"(v));
    return make_float2(lo, hi);
}

// ---------------------------------------------------------------------------
// Kernel 1: log_prob_matrix + exp(log_prob) scratch. (EXACT round-4 version)
// ---------------------------------------------------------------------------
__global__ __launch_bounds__(K1_THREADS)
void k_logprob(const float* __restrict__ ml,     // [B, TT, 2*NC]
               const float* __restrict__ mel,    // [B, NC, MM]
               float* __restrict__ lpm)          // [B, TT, MM] (d_out + 1)
{
    extern __shared__ char sm[];
    unsigned long long* X2s = (unsigned long long*)(sm + SM_X2_OFF); // [NC][64]
    unsigned long long* Xs  = (unsigned long long*)(sm + SM_X_OFF);  // [NC][64]
    float2* wa = (float2*)(sm + SM_WA_OFF);  // [TBLK][NC] = {w, a}
    float*  kp = (float*) (sm + SM_KP_OFF);  // [TBLK][4]
    float*  kc = (float*) (sm + SM_KC_OFF);  // [TBLK]

    const int b   = blockIdx.z;
    const int t0  = blockIdx.y * TBLK;
    const int m0  = blockIdx.x * MBLK;
    const int tid = threadIdx.x;

    // Phase A: per-t coefficients. thread -> (t = tid/4, c-lane = tid%4)
    {
        const int t  = tid >> 2;
        const int cl = tid & 3;
        const float* row = ml + ((size_t)(b * TT + t0 + t)) * (2 * NC);
        float kpart = 0.f;
#pragma unroll
        for (int i = 0; i < 20; i++) {
            int c = cl + 4 * i;
            float mu = row[c];
            float lv = row[NC + c];
            float w  = __expf(-lv);
            float a  = -2.f * w * mu;
            wa[t * NC + c] = make_float2(w, a);
            kpart += __fmaf_rn(w * mu, mu, lv);
        }
        kp[t * 4 + cl] = kpart;
    }

    // Phase B: melspec tile -> packed (x2 pair) and (x pair)
    for (int lin = tid; lin < NC * 64; lin += K1_THREADS) {
        int c = lin >> 6;
        int p = lin & 63;
        float2 x = ((const float2*)(mel + ((size_t)(b * NC + c)) * MM + m0))[p];
        X2s[c * 64 + p] = pack2(x.x * x.x, x.y * x.y);
        Xs [c * 64 + p] = pack2(x.x, x.y);
    }
    __syncthreads();

    if (tid < TBLK) {
        kc[tid] = kp[tid*4] + kp[tid*4+1] + kp[tid*4+2] + kp[tid*4+3];
    }
    __syncthreads();

    // Phase C: FFMA2 micro-tile 4t x 4 m-pairs
    const int tx = tid & 15;     // m-pair lane
    const int ty = tid >> 4;     // t group (4 consecutive t)
    unsigned long long acc[4][4];
#pragma unroll
    for (int tt = 0; tt < 4; tt++)
#pragma unroll
        for (int j = 0; j < 4; j++) acc[tt][j] = 0ull;

#pragma unroll 2
    for (int c = 0; c < NC; c++) {
        unsigned long long x2p[4], xp[4];
#pragma unroll
        for (int j = 0; j < 4; j++) {
            x2p[j] = X2s[c * 64 + tx + 16 * j];
            xp[j]  = Xs [c * 64 + tx + 16 * j];
        }
#pragma unroll
        for (int tt = 0; tt < 4; tt++) {
            float2 wv = wa[(4 * ty + tt) * NC + c];
            unsigned long long ww = pack2(wv.x, wv.x);
            unsigned long long aa = pack2(wv.y, wv.y);
#pragma unroll
            for (int j = 0; j < 4; j++) {
                fma2(acc[tt][j], ww, x2p[j]);
                fma2(acc[tt][j], aa, xp[j]);
            }
        }
    }

    // Epilogue
    const float inv = -1.f / (2.f * NC);
    float kt[4];
#pragma unroll
    for (int tt = 0; tt < 4; tt++) kt[tt] = kc[4 * ty + tt];
    const int tg = t0 + 4 * ty;

#pragma unroll
    for (int j = 0; j < 4; j++) {
        const int me = m0 + 2 * (tx + 16 * j);   // even m
        float e0[4], e1[4];
#pragma unroll
        for (int tt = 0; tt < 4; tt++) {
            float2 v = unpack2(acc[tt][j]);
            float lp0 = (v.x + kt[tt]) * inv;
            float lp1 = (v.y + kt[tt]) * inv;
            float* dst = lpm + ((size_t)(b * TT + tg + tt)) * MM + me;
            dst[0] = lp0;          // d_out+1 is only 4B aligned: scalar stores
            dst[1] = lp1;
            e0[tt] = __expf(lp0);
            e1[tt] = __expf(lp1);
        }
        *(float4*)(g_elp + ((size_t)b * MM + me)     * TT + tg) =
            make_float4(e0[0], e0[1], e0[2], e0[3]);
        *(float4*)(g_elp + ((size_t)b * MM + me + 1) * TT + tg) =
            make_float4(e1[0], e1[1], e1[2], e1[3]);
    }
}

// ---------------------------------------------------------------------------
// Kernel 2 (k_scanf): fully fused chunked scan. One block per batch, 512 thr.
// Each iteration (8 total) covers 64 steps: 4 groups of 128 threads build
// 16-step banded transfer matrices IN PARALLEL (smem only), then q is updated
// by 4 sequential banded matvecs.
// FIX vs round 9: exact 2^k q-rescale after EVERY matvec (round-7 cadence).
// Four unrescaled matvecs compounded to <1e-40 -> fp32 zero -> log(0) = -inf.
// ---------------------------------------------------------------------------
__global__ __launch_bounds__(512)
void k_scanf(float* __restrict__ out_base,       // d_out (out[0]=loss, +1=lpm)
             const int* __restrict__ tlen,
             const int* __restrict__ mlen)
{
    extern __shared__ float smf[];
    float* EB = smf;                    // [2][64][128] staged E tiles
    float* BS = smf + 2 * 64 * 128;     // [4][17][128] band matrices
    float* QS = BS + 4 * 17 * 128;      // [2][128] q ping-pong
    float* WR = QS + 2 * 128;           // [16] per-warp band maxes
    float* WM = WR + 16;                // [4] q-rescale staging

    const int b    = blockIdx.x;
    const int tid  = threadIdx.x;
    const int lane = tid & 31;
    const int warp = tid >> 5;          // 0..15
    const int g    = tid >> 7;          // group 0..3
    const int j    = tid & 127;         // column within group
    const int last = mlen[b] - 1;
    const int txt_len = tlen[b];
    const float L0 = out_base[1 + (size_t)b * TT * MM];   // lp[b,0,0]
    int kTot = 0;                       // only thread 0's copy is used

    if (tid < 128) QS[tid] = (tid == 0) ? 1.f : 0.f;

    const float* Eb = g_elp + (size_t)b * MM * TT;

    // prologue: async-copy E tile for it=0 into buffer 0
#pragma unroll
    for (int i = 0; i < 4; i++) {
        int ff = tid + 512 * i;         // float4 index into [64][32]
        int rho = ff >> 5, c4 = ff & 31;
        const float* src = Eb + (size_t)(1 + rho) * TT + 4 * c4;
        uint32_t dst = (uint32_t)__cvta_generic_to_shared(EB + rho * 128 + 4 * c4);
        asm volatile("cp.async.cg.shared.global [%0], [%1], 16;"
                     :: "r"(dst), "l"(src));
    }
    asm volatile("cp.async.commit_group;");

    for (int it = 0; it < NIT; it++) {
        const int buf = it & 1;
        // prefetch next E tile; wait for current
        if (it + 1 < NIT) {
#pragma unroll
            for (int i = 0; i < 4; i++) {
                int ff = tid + 512 * i;
                int rho = ff >> 5, c4 = ff & 31;
                const float* src = Eb + (size_t)(1 + 64 * (it + 1) + rho) * TT + 4 * c4;
                uint32_t dst = (uint32_t)__cvta_generic_to_shared(
                    EB + (1 - buf) * 8192 + rho * 128 + 4 * c4);
                asm volatile("cp.async.cg.shared.global [%0], [%1], 16;"
                             :: "r"(dst), "l"(src));
            }
            asm volatile("cp.async.commit_group;");
            asm volatile("cp.async.wait_group 1;");
        } else {
            asm volatile("cp.async.wait_group 0;");
        }
        __syncthreads();                // E(it) visible block-wide

        // --- build band for this thread's group (16 steps, width 17) ---
        float band[17];
        band[0] = 1.f;
#pragma unroll
        for (int k = 1; k <= 16; k++) band[k] = 0.f;
        const int mg = 1 + 64 * it + 16 * g;
        const float* Erow0 = EB + buf * 8192 + (16 * g) * 128;
#pragma unroll
        for (int s = 0; s < CSF; s++) {
            if (mg + s <= last) {       // uniform per group (warps don't straddle)
                const float* row = Erow0 + s * 128;
#pragma unroll
                for (int k = 16; k >= 1; k--) {
                    if (k <= s + 1) {
                        int r = j + k; r = (r > 127) ? 127 : r;  // dead-lane clamp
                        band[k] = (band[k] + band[k - 1]) * row[r];
                    }
                }
                band[0] *= row[j];
            }
        }

        // per-group band max (parallel across groups)
        float mx = band[0];
#pragma unroll
        for (int k = 1; k <= 16; k++) mx = fmaxf(mx, band[k]);
#pragma unroll
        for (int o = 16; o; o >>= 1)
            mx = fmaxf(mx, __shfl_xor_sync(0xffffffffu, mx, o));
        if (lane == 0) WR[warp] = mx;
        // store raw band
#pragma unroll
        for (int k = 0; k <= 16; k++) BS[(g * 17 + k) * 128 + j] = band[k];
        __syncthreads();

        // per-group 2^k scales (uniform; applied to matvec results)
        float sc[4];
#pragma unroll
        for (int gg = 0; gg < 4; gg++) {
            float m2 = fmaxf(fmaxf(WR[4 * gg], WR[4 * gg + 1]),
                             fmaxf(WR[4 * gg + 2], WR[4 * gg + 3]));
            if (m2 > 0.f) {
                int eb2 = (__float_as_int(m2) >> 23) & 0xff;
                sc[gg] = __int_as_float((254 - eb2) << 23);
                if (tid == 0) kTot += eb2 - 127;
            } else sc[gg] = 1.f;
        }

        // --- 4 sequential banded matvecs, q-rescale after EVERY matvec ---
#pragma unroll
        for (int gg = 0; gg < 4; gg++) {
            const int p = gg & 1;       // read buffer
            float val = 0.f;
            if (tid < 128) {
                float a0 = 0.f, a1 = 0.f, a2 = 0.f, a3 = 0.f;
#pragma unroll
                for (int k = 0; k <= 16; k++) {
                    int jc = j - k;
                    float v = (jc >= 0)
                        ? BS[(gg * 17 + k) * 128 + jc] * QS[p * 128 + jc] : 0.f;
                    if ((k & 3) == 0) a0 += v;
                    else if ((k & 3) == 1) a1 += v;
                    else if ((k & 3) == 2) a2 += v;
                    else a3 += v;
                }
                val = ((a0 + a1) + (a2 + a3)) * sc[gg];
                // per-matvec q max (warps 0..3)
                float m3 = val;
#pragma unroll
                for (int o = 16; o; o >>= 1)
                    m3 = fmaxf(m3, __shfl_xor_sync(0xffffffffu, m3, o));
                if (lane == 0) WM[warp] = m3;
            }
            __syncthreads();
            float qmx = fmaxf(fmaxf(WM[0], WM[1]), fmaxf(WM[2], WM[3]));
            float qsc = 1.f;
            if (qmx > 0.f) {
                int eb3 = (__float_as_int(qmx) >> 23) & 0xff;
                qsc = __int_as_float((254 - eb3) << 23);
                if (tid == 0) kTot += eb3 - 127;
            }
            if (tid < 128) QS[(1 - p) * 128 + j] = val * qsc;
            __syncthreads();
        }
    }

    // epilogue: alpha extraction + fused loss reduction (proven ticket)
    if (tid == 0) {
        float v = QS[txt_len - 1];      // final q lives in buffer 0
        float alpha = __logf(v) + (float)kTot * 0.69314718055994531f + L0;
        g_alpha[b] = alpha / (float)mlen[b];
        __threadfence();
        unsigned ticket = atomicAdd(&g_cnt, 1u);
        if (ticket == BB - 1) {
            __threadfence();
            float sum = 0.f;
#pragma unroll
            for (int k = 0; k < BB; k++)
                sum += ((volatile float*)g_alpha)[k];
            out_base[0] = -sum * (1.f / BB);
            g_cnt = 0;   // reset for next graph replay
        }
    }
}

// ---------------------------------------------------------------------------
extern "C" void kernel_launch(void* const* d_in, const int* in_sizes, int n_in,
                              void* d_out, int out_size)
{
    const float* ml  = (const float*)d_in[0];   // mu_logvar [16,128,160]
    const float* mel = (const float*)d_in[1];   // melspec   [16,80,512]
    const int*   tl  = (const int*)d_in[2];     // text_lengths [16]
    const int*   mll = (const int*)d_in[3];     // mel_lengths  [16]
    float* out = (float*)d_out;                 // [0]=loss, [1..]=log_prob_matrix

    cudaFuncSetAttribute(k_logprob,
                         cudaFuncAttributeMaxDynamicSharedMemorySize, SM_TOTAL);
    cudaFuncSetAttribute(k_scanf,
                         cudaFuncAttributeMaxDynamicSharedMemorySize, SMEM_SCANF);

    k_logprob<<<dim3(MM / MBLK, TT / TBLK, BB), K1_THREADS, SM_TOTAL>>>(
        ml, mel, out + 1);
    k_scanf<<<BB, 512, SMEM_SCANF>>>(out, tl, mll);
}

// round 11
// speedup vs baseline: 1.3409x; 1.3409x over previous
#include <cuda_runtime.h>
#include <cuda_bf16.h>
#include <cstdint>

// Problem constants (fixed by the dataset)
#define BB  16
#define TT  128   // txt_T
#define MM  512   // mel_T
#define NC  80    // N_MEL

// k_logprob tiling (exact round-4 proven shape)
#define TBLK 32
#define MBLK 128
#define K1_THREADS 128

// Scratch (no cudaMalloc allowed). Pad: refills overshoot by <= 32 rows.
__device__ __align__(16) float g_elp[(size_t)BB * MM * TT + 4096]; // exp(lp), [b][m][t]
__device__ float g_alpha[BB];
__device__ unsigned g_cnt = 0;

// smem layout (bytes) for k_logprob (round-4)
#define SM_X2_OFF 0
#define SM_X_OFF  (NC * 64 * 8)                 // 40960
#define SM_WA_OFF (SM_X_OFF + NC * 64 * 8)      // 81920
#define SM_KP_OFF (SM_WA_OFF + TBLK * NC * 8)   // 102400
#define SM_KC_OFF (SM_KP_OFF + TBLK * 4 * 4)    // 102912
#define SM_TOTAL  (SM_KC_OFF + TBLK * 4)        // 103040

// ---- packed f32x2 helpers (sm_103a dual-fp32 pipe; PTX-only) ----
__device__ __forceinline__ void fma2(unsigned long long& d,
                                     unsigned long long a,
                                     unsigned long long b) {
    asm("fma.rn.f32x2 %0, %1, %2, %0;" : "+l"(d) : "l"(a), "l"(b));
}
__device__ __forceinline__ unsigned long long pack2(float lo, float hi) {
    unsigned long long r;
    asm("mov.b64 %0, {%1, %2};" : "=l"(r) : "f"(lo), "f"(hi));
    return r;
}
__device__ __forceinline__ float2 unpack2(unsigned long long v) {
    float lo, hi;
    asm("mov.b64 {%0, %1}, %2;" : "=f"(lo), "=f"(hi) : "l"(v));
    return make_float2(lo, hi);
}

// ---------------------------------------------------------------------------
// Kernel 1: log_prob_matrix + exp(log_prob) scratch. (EXACT round-4 version)
// ---------------------------------------------------------------------------
__global__ __launch_bounds__(K1_THREADS)
void k_logprob(const float* __restrict__ ml,     // [B, TT, 2*NC]
               const float* __restrict__ mel,    // [B, NC, MM]
               float* __restrict__ lpm)          // [B, TT, MM] (d_out + 1)
{
    extern __shared__ char sm[];
    unsigned long long* X2s = (unsigned long long*)(sm + SM_X2_OFF); // [NC][64]
    unsigned long long* Xs  = (unsigned long long*)(sm + SM_X_OFF);  // [NC][64]
    float2* wa = (float2*)(sm + SM_WA_OFF);  // [TBLK][NC] = {w, a}
    float*  kp = (float*) (sm + SM_KP_OFF);  // [TBLK][4]
    float*  kc = (float*) (sm + SM_KC_OFF);  // [TBLK]

    const int b   = blockIdx.z;
    const int t0  = blockIdx.y * TBLK;
    const int m0  = blockIdx.x * MBLK;
    const int tid = threadIdx.x;

    // Phase A: per-t coefficients. thread -> (t = tid/4, c-lane = tid%4)
    {
        const int t  = tid >> 2;
        const int cl = tid & 3;
        const float* row = ml + ((size_t)(b * TT + t0 + t)) * (2 * NC);
        float kpart = 0.f;
#pragma unroll
        for (int i = 0; i < 20; i++) {
            int c = cl + 4 * i;
            float mu = row[c];
            float lv = row[NC + c];
            float w  = __expf(-lv);
            float a  = -2.f * w * mu;
            wa[t * NC + c] = make_float2(w, a);
            kpart += __fmaf_rn(w * mu, mu, lv);
        }
        kp[t * 4 + cl] = kpart;
    }

    // Phase B: melspec tile -> packed (x2 pair) and (x pair)
    for (int lin = tid; lin < NC * 64; lin += K1_THREADS) {
        int c = lin >> 6;
        int p = lin & 63;
        float2 x = ((const float2*)(mel + ((size_t)(b * NC + c)) * MM + m0))[p];
        X2s[c * 64 + p] = pack2(x.x * x.x, x.y * x.y);
        Xs [c * 64 + p] = pack2(x.x, x.y);
    }
    __syncthreads();

    if (tid < TBLK) {
        kc[tid] = kp[tid*4] + kp[tid*4+1] + kp[tid*4+2] + kp[tid*4+3];
    }
    __syncthreads();

    // Phase C: FFMA2 micro-tile 4t x 4 m-pairs
    const int tx = tid & 15;     // m-pair lane
    const int ty = tid >> 4;     // t group (4 consecutive t)
    unsigned long long acc[4][4];
#pragma unroll
    for (int tt = 0; tt < 4; tt++)
#pragma unroll
        for (int j = 0; j < 4; j++) acc[tt][j] = 0ull;

#pragma unroll 2
    for (int c = 0; c < NC; c++) {
        unsigned long long x2p[4], xp[4];
#pragma unroll
        for (int j = 0; j < 4; j++) {
            x2p[j] = X2s[c * 64 + tx + 16 * j];
            xp[j]  = Xs [c * 64 + tx + 16 * j];
        }
#pragma unroll
        for (int tt = 0; tt < 4; tt++) {
            float2 wv = wa[(4 * ty + tt) * NC + c];
            unsigned long long ww = pack2(wv.x, wv.x);
            unsigned long long aa = pack2(wv.y, wv.y);
#pragma unroll
            for (int j = 0; j < 4; j++) {
                fma2(acc[tt][j], ww, x2p[j]);
                fma2(acc[tt][j], aa, xp[j]);
            }
        }
    }

    // Epilogue
    const float inv = -1.f / (2.f * NC);
    float kt[4];
#pragma unroll
    for (int tt = 0; tt < 4; tt++) kt[tt] = kc[4 * ty + tt];
    const int tg = t0 + 4 * ty;

#pragma unroll
    for (int j = 0; j < 4; j++) {
        const int me = m0 + 2 * (tx + 16 * j);   // even m
        float e0[4], e1[4];
#pragma unroll
        for (int tt = 0; tt < 4; tt++) {
            float2 v = unpack2(acc[tt][j]);
            float lp0 = (v.x + kt[tt]) * inv;
            float lp1 = (v.y + kt[tt]) * inv;
            float* dst = lpm + ((size_t)(b * TT + tg + tt)) * MM + me;
            dst[0] = lp0;          // d_out+1 is only 4B aligned: scalar stores
            dst[1] = lp1;
            e0[tt] = __expf(lp0);
            e1[tt] = __expf(lp1);
        }
        *(float4*)(g_elp + ((size_t)b * MM + me)     * TT + tg) =
            make_float4(e0[0], e0[1], e0[2], e0[3]);
        *(float4*)(g_elp + ((size_t)b * MM + me + 1) * TT + tg) =
            make_float4(e1[0], e1[1], e1[2], e1[3]);
    }
}

// ---------------------------------------------------------------------------
// Kernel 2: probability-domain serial scan (round-4 structure) with TWO
// numerically-identical scheduling changes:
//  (1) shfl hoisted: n3 computed first, shfl(n3) issued immediately, its
//      result consumed only by the NEXT step's n0 (a full step of slack
//      instead of ~4 instructions -> hides the ~30cyc SHFL latency).
//  (2) rescale max via one redux.sync.max.u32 (q > 0 so u32-max == fp-max)
//      instead of a 5-shfl serial reduce. The pipelined `top` is scaled
//      along with q (it was produced pre-rescale).
// Batched A/B half-ring refills, rescale every 16 steps, select-freeze tail:
// all exactly as the passing round-4 kernel.
// ---------------------------------------------------------------------------
__global__ __launch_bounds__(32)
void k_scan(const float* __restrict__ out_base,  // d_out (out[0]=loss, +1=lpm)
            const int* __restrict__ tlen,
            const int* __restrict__ mlen)
{
    const int b    = blockIdx.x;
    const int lane = threadIdx.x;
    const float4* __restrict__ Ev =
        (const float4*)(g_elp + (size_t)b * MM * TT);   // [m][32 lanes]

    const int mel_len = mlen[b];
    const int txt_len = tlen[b];
    const int last    = mel_len - 1;          // >= 255 for this dataset

    float q0 = (lane == 0) ? 1.f : 0.f;
    float q1 = 0.f, q2 = 0.f, q3 = 0.f;
    float top = 0.f;                          // boundary value for the NEXT step
    const bool isL0 = (lane == 0);
    const float L0 = out_base[1 + (size_t)b * TT * MM];  // lp[b,0,0]
    int kTot = 0;

    // hoisted-shfl step: shfl(n3) issues early, consumed next step via `top`
#define STEPQ_H(e)                                                \
    {                                                             \
        float n3 = (q3 + q2) * (e).w;                             \
        float tn = __shfl_up_sync(0xffffffffu, n3, 1);            \
        float n2 = (q2 + q1) * (e).z;                             \
        float n1 = (q1 + q0) * (e).y;                             \
        float n0 = (q0 + top) * (e).x;                            \
        top = isL0 ? 0.f : tn;                                    \
        q0 = n0; q1 = n1; q2 = n2; q3 = n3;                       \
    }

    // exact 2^k rescale via redux (u32 max == fp max for q >= 0); scales the
    // pipelined `top` too (it was produced from pre-rescale q3).
#define RESCALE_R()                                               \
    {                                                             \
        float mxq = fmaxf(fmaxf(q0, q1), fmaxf(q2, q3));          \
        unsigned mb;                                              \
        asm("redux.sync.max.u32 %0, %1, 0xffffffff;"              \
            : "=r"(mb) : "r"(__float_as_uint(mxq)));              \
        if (mb != 0u) {                                           \
            int eb = (int)(mb >> 23) & 0xff;                      \
            float sc = __int_as_float((254 - eb) << 23);          \
            q0 *= sc; q1 *= sc; q2 *= sc; q3 *= sc;               \
            top *= sc;                                            \
            kTot += eb - 127;                                     \
        }                                                         \
    }

    // proven round-4 tail step (self-contained shfl, select freeze)
#define STEPQ_PRED(e, act)                                        \
    {                                                             \
        float tp = __shfl_up_sync(0xffffffffu, q3, 1);            \
        if (isL0) tp = 0.f;                                       \
        float n0 = (q0 + tp) * (e).x;                             \
        float n1 = (q1 + q0) * (e).y;                             \
        float n2 = (q2 + q1) * (e).z;                             \
        float n3 = (q3 + q2) * (e).w;                             \
        q0 = (act) ? n0 : q0;                                     \
        q1 = (act) ? n1 : q1;                                     \
        q2 = (act) ? n2 : q2;                                     \
        q3 = (act) ? n3 : q3;                                     \
    }

    // Double-buffered half-rings: A holds m..m+15, B holds m+16..m+31.
    float4 A[16], Bf[16];
#pragma unroll
    for (int i = 0; i < 16; i++) A[i]  = Ev[(size_t)(1 + i) * 32 + lane];
#pragma unroll
    for (int i = 0; i < 16; i++) Bf[i] = Ev[(size_t)(17 + i) * 32 + lane];

    int m = 1;
    while (m + 31 <= last) {
        // consume A (steps m..m+15)
#pragma unroll
        for (int i = 0; i < 16; i++) STEPQ_H(A[i]);
        // batched refill A <- m+32..m+47 (clamped to valid region)
#pragma unroll
        for (int i = 0; i < 16; i++) {
            int mi = m + 32 + i; if (mi > MM - 1) mi = MM - 1;
            A[i] = Ev[(size_t)mi * 32 + lane];
        }
        RESCALE_R();

        // consume B (steps m+16..m+31)
#pragma unroll
        for (int i = 0; i < 16; i++) STEPQ_H(Bf[i]);
        // batched refill B <- m+48..m+63 (clamped)
#pragma unroll
        for (int i = 0; i < 16; i++) {
            int mi = m + 48 + i; if (mi > MM - 1) mi = MM - 1;
            Bf[i] = Ev[(size_t)mi * 32 + lane];
        }
        RESCALE_R();
        m += 32;
    }

    // tail: <= 31 remaining steps; rings hold m..m+31. `top` is discarded —
    // the tail step recomputes its shuffle from q3 (same value, same result).
#pragma unroll
    for (int i = 0; i < 16; i++) STEPQ_PRED(A[i],  (m + i)      <= last);
#pragma unroll
    for (int i = 0; i < 16; i++) STEPQ_PRED(Bf[i], (m + 16 + i) <= last);

#undef STEPQ_H
#undef RESCALE_R
#undef STEPQ_PRED

    // extract alpha_last, fold loss reduction (proven ticket scheme)
    {
        const int idx = txt_len - 1;
        const int sel = idx & 3;
        float v = (sel == 0) ? q0 : (sel == 1) ? q1 : (sel == 2) ? q2 : q3;
        v = __shfl_sync(0xffffffffu, v, idx >> 2);
        if (lane == 0) {
            float alpha = __logf(v) + (float)kTot * 0.69314718055994531f + L0;
            g_alpha[b] = alpha / (float)mel_len;
            __threadfence();
            unsigned ticket = atomicAdd(&g_cnt, 1u);
            if (ticket == BB - 1) {
                __threadfence();
                float s = 0.f;
#pragma unroll
                for (int i = 0; i < BB; i++)
                    s += ((volatile float*)g_alpha)[i];
                ((float*)out_base)[0] = -s * (1.f / BB);
                g_cnt = 0;   // reset for next graph replay
            }
        }
    }
}

// ---------------------------------------------------------------------------
extern "C" void kernel_launch(void* const* d_in, const int* in_sizes, int n_in,
                              void* d_out, int out_size)
{
    const float* ml  = (const float*)d_in[0];   // mu_logvar [16,128,160]
    const float* mel = (const float*)d_in[1];   // melspec   [16,80,512]
    const int*   tl  = (const int*)d_in[2];     // text_lengths [16]
    const int*   mll = (const int*)d_in[3];     // mel_lengths  [16]
    float* out = (float*)d_out;                 // [0]=loss, [1..]=log_prob_matrix

    cudaFuncSetAttribute(k_logprob,
                         cudaFuncAttributeMaxDynamicSharedMemorySize, SM_TOTAL);

    k_logprob<<<dim3(MM / MBLK, TT / TBLK, BB), K1_THREADS, SM_TOTAL>>>(
        ml, mel, out + 1);
    k_scan<<<BB, 32>>>(out, tl, mll);
}

// round 12
// speedup vs baseline: 1.5046x; 1.1221x over previous
#include <cuda_runtime.h>
#include <cuda_bf16.h>
#include <cstdint>

// Problem constants (fixed by the dataset)
#define BB  16
#define TT  128   // txt_T
#define MM  512   // mel_T
#define NC  80    // N_MEL

// k_logprob tiling (exact round-4 proven shape)
#define TBLK 32
#define MBLK 128
#define K1_THREADS 128

// Scratch (no cudaMalloc allowed).
__device__ __align__(16) float g_elp[(size_t)BB * MM * TT + 4096]; // exp(lp), [b][m][t]
__device__ float g_alpha[BB];
__device__ unsigned g_cnt = 0;

// smem layout (bytes) for k_logprob (round-4)
#define SM_X2_OFF 0
#define SM_X_OFF  (NC * 64 * 8)                 // 40960
#define SM_WA_OFF (SM_X_OFF + NC * 64 * 8)      // 81920
#define SM_KP_OFF (SM_WA_OFF + TBLK * NC * 8)   // 102400
#define SM_KC_OFF (SM_KP_OFF + TBLK * 4 * 4)    // 102912
#define SM_TOTAL  (SM_KC_OFF + TBLK * 4)        // 103040

// ---- packed f32x2 helpers (sm_103a dual-fp32 pipe; PTX-only) ----
__device__ __forceinline__ void fma2(unsigned long long& d,
                                     unsigned long long a,
                                     unsigned long long b) {
    asm("fma.rn.f32x2 %0, %1, %2, %0;" : "+l"(d) : "l"(a), "l"(b));
}
__device__ __forceinline__ unsigned long long pack2(float lo, float hi) {
    unsigned long long r;
    asm("mov.b64 %0, {%1, %2};" : "=l"(r) : "f"(lo), "f"(hi));
    return r;
}
__device__ __forceinline__ float2 unpack2(unsigned long long v) {
    float lo, hi;
    asm("mov.b64 {%0, %1}, %2;" : "=f"(lo), "=f"(hi) : "l"(v));
    return make_float2(lo, hi);
}

// ---------------------------------------------------------------------------
// Kernel 1: log_prob_matrix + exp(log_prob) scratch. (EXACT round-4 version)
// ---------------------------------------------------------------------------
__global__ __launch_bounds__(K1_THREADS)
void k_logprob(const float* __restrict__ ml,     // [B, TT, 2*NC]
               const float* __restrict__ mel,    // [B, NC, MM]
               float* __restrict__ lpm)          // [B, TT, MM] (d_out + 1)
{
    extern __shared__ char sm[];
    unsigned long long* X2s = (unsigned long long*)(sm + SM_X2_OFF); // [NC][64]
    unsigned long long* Xs  = (unsigned long long*)(sm + SM_X_OFF);  // [NC][64]
    float2* wa = (float2*)(sm + SM_WA_OFF);  // [TBLK][NC] = {w, a}
    float*  kp = (float*) (sm + SM_KP_OFF);  // [TBLK][4]
    float*  kc = (float*) (sm + SM_KC_OFF);  // [TBLK]

    const int b   = blockIdx.z;
    const int t0  = blockIdx.y * TBLK;
    const int m0  = blockIdx.x * MBLK;
    const int tid = threadIdx.x;

    // Phase A: per-t coefficients. thread -> (t = tid/4, c-lane = tid%4)
    {
        const int t  = tid >> 2;
        const int cl = tid & 3;
        const float* row = ml + ((size_t)(b * TT + t0 + t)) * (2 * NC);
        float kpart = 0.f;
#pragma unroll
        for (int i = 0; i < 20; i++) {
            int c = cl + 4 * i;
            float mu = row[c];
            float lv = row[NC + c];
            float w  = __expf(-lv);
            float a  = -2.f * w * mu;
            wa[t * NC + c] = make_float2(w, a);
            kpart += __fmaf_rn(w * mu, mu, lv);
        }
        kp[t * 4 + cl] = kpart;
    }

    // Phase B: melspec tile -> packed (x2 pair) and (x pair)
    for (int lin = tid; lin < NC * 64; lin += K1_THREADS) {
        int c = lin >> 6;
        int p = lin & 63;
        float2 x = ((const float2*)(mel + ((size_t)(b * NC + c)) * MM + m0))[p];
        X2s[c * 64 + p] = pack2(x.x * x.x, x.y * x.y);
        Xs [c * 64 + p] = pack2(x.x, x.y);
    }
    __syncthreads();

    if (tid < TBLK) {
        kc[tid] = kp[tid*4] + kp[tid*4+1] + kp[tid*4+2] + kp[tid*4+3];
    }
    __syncthreads();

    // Phase C: FFMA2 micro-tile 4t x 4 m-pairs
    const int tx = tid & 15;     // m-pair lane
    const int ty = tid >> 4;     // t group (4 consecutive t)
    unsigned long long acc[4][4];
#pragma unroll
    for (int tt = 0; tt < 4; tt++)
#pragma unroll
        for (int j = 0; j < 4; j++) acc[tt][j] = 0ull;

#pragma unroll 2
    for (int c = 0; c < NC; c++) {
        unsigned long long x2p[4], xp[4];
#pragma unroll
        for (int j = 0; j < 4; j++) {
            x2p[j] = X2s[c * 64 + tx + 16 * j];
            xp[j]  = Xs [c * 64 + tx + 16 * j];
        }
#pragma unroll
        for (int tt = 0; tt < 4; tt++) {
            float2 wv = wa[(4 * ty + tt) * NC + c];
            unsigned long long ww = pack2(wv.x, wv.x);
            unsigned long long aa = pack2(wv.y, wv.y);
#pragma unroll
            for (int j = 0; j < 4; j++) {
                fma2(acc[tt][j], ww, x2p[j]);
                fma2(acc[tt][j], aa, xp[j]);
            }
        }
    }

    // Epilogue
    const float inv = -1.f / (2.f * NC);
    float kt[4];
#pragma unroll
    for (int tt = 0; tt < 4; tt++) kt[tt] = kc[4 * ty + tt];
    const int tg = t0 + 4 * ty;

#pragma unroll
    for (int j = 0; j < 4; j++) {
        const int me = m0 + 2 * (tx + 16 * j);   // even m
        float e0[4], e1[4];
#pragma unroll
        for (int tt = 0; tt < 4; tt++) {
            float2 v = unpack2(acc[tt][j]);
            float lp0 = (v.x + kt[tt]) * inv;
            float lp1 = (v.y + kt[tt]) * inv;
            float* dst = lpm + ((size_t)(b * TT + tg + tt)) * MM + me;
            dst[0] = lp0;          // d_out+1 is only 4B aligned: scalar stores
            dst[1] = lp1;
            e0[tt] = __expf(lp0);
            e1[tt] = __expf(lp1);
        }
        *(float4*)(g_elp + ((size_t)b * MM + me)     * TT + tg) =
            make_float4(e0[0], e0[1], e0[2], e0[3]);
        *(float4*)(g_elp + ((size_t)b * MM + me + 1) * TT + tg) =
            make_float4(e1[0], e1[1], e1[2], e1[3]);
    }
}

// ---------------------------------------------------------------------------
// Kernel 2: probability-domain serial scan. ONE change vs the passing R11
// kernel: the E ring moves from 128 REGISTERS (suspected spill to local mem,
// ~35cyc LDL on every step's critical path) to SHARED memory fed by cp.async
// (global -> smem, no register traffic). Two 32-row buffers, 2-deep group
// pipeline, LDS.128 per step with a depth-2 register e-prefetch. Each lane
// reads exactly the 16B it copied -> no intra-warp smem sync needed.
// Step math, rescale cadence (every 16, redux), hoisted shfl, select-freeze
// tail, ticket epilogue: bit-identical to R11 (passing, rel_err 7.4e-5).
// ---------------------------------------------------------------------------
__global__ __launch_bounds__(32)
void k_scan(const float* __restrict__ out_base,  // d_out (out[0]=loss, +1=lpm)
            const int* __restrict__ tlen,
            const int* __restrict__ mlen)
{
    __shared__ __align__(16) float SE[64 * 128];  // 2 buffers x 32 rows x 128 t

    const int b    = blockIdx.x;
    const int lane = threadIdx.x;
    const float* Eb = g_elp + (size_t)b * MM * TT;   // [m][128]

    const int mel_len = mlen[b];
    const int txt_len = tlen[b];
    const int last    = mel_len - 1;          // >= 255 for this dataset

    float q0 = (lane == 0) ? 1.f : 0.f;
    float q1 = 0.f, q2 = 0.f, q3 = 0.f;
    float top = 0.f;
    const bool isL0 = (lane == 0);
    const float L0 = out_base[1 + (size_t)b * TT * MM];  // lp[b,0,0]
    int kTot = 0;

    const uint32_t se_base =
        (uint32_t)__cvta_generic_to_shared(SE) + lane * 16;

    // issue one 32-row chunk (k) into buffer k&1 via cp.async (rows clamped)
#define ISSUE_CHUNK(kk)                                               \
    {                                                                 \
        uint32_t d0 = se_base + ((kk) & 1) * 16384;                   \
        _Pragma("unroll")                                             \
        for (int s = 0; s < 32; s++) {                                \
            int row = 1 + 32 * (kk) + s;                              \
            if (row > MM - 1) row = MM - 1;                           \
            const float* src = Eb + (size_t)row * TT + lane * 4;      \
            asm volatile("cp.async.cg.shared.global [%0], [%1], 16;"  \
                         :: "r"(d0 + s * 512), "l"(src));             \
        }                                                             \
        asm volatile("cp.async.commit_group;");                       \
    }

    // hoisted-shfl step (R11, proven)
#define STEPQ_H(e)                                                \
    {                                                             \
        float n3 = (q3 + q2) * (e).w;                             \
        float tn = __shfl_up_sync(0xffffffffu, n3, 1);            \
        float n2 = (q2 + q1) * (e).z;                             \
        float n1 = (q1 + q0) * (e).y;                             \
        float n0 = (q0 + top) * (e).x;                            \
        top = isL0 ? 0.f : tn;                                    \
        q0 = n0; q1 = n1; q2 = n2; q3 = n3;                       \
    }

    // exact 2^k rescale via redux (R11, proven); scales pipelined `top` too
#define RESCALE_R()                                               \
    {                                                             \
        float mxq = fmaxf(fmaxf(q0, q1), fmaxf(q2, q3));          \
        unsigned mb;                                              \
        asm("redux.sync.max.u32 %0, %1, 0xffffffff;"              \
            : "=r"(mb) : "r"(__float_as_uint(mxq)));              \
        if (mb != 0u) {                                           \
            int eb = (int)(mb >> 23) & 0xff;                      \
            float sc = __int_as_float((254 - eb) << 23);          \
            q0 *= sc; q1 *= sc; q2 *= sc; q3 *= sc;               \
            top *= sc;                                            \
            kTot += eb - 127;                                     \
        }                                                         \
    }

    // tail step (R4, proven): self-contained shfl, select freeze
#define STEPQ_PRED(e, act)                                        \
    {                                                             \
        float tp = __shfl_up_sync(0xffffffffu, q3, 1);            \
        if (isL0) tp = 0.f;                                       \
        float n0 = (q0 + tp) * (e).x;                             \
        float n1 = (q1 + q0) * (e).y;                             \
        float n2 = (q2 + q1) * (e).z;                             \
        float n3 = (q3 + q2) * (e).w;                             \
        q0 = (act) ? n0 : q0;                                     \
        q1 = (act) ? n1 : q1;                                     \
        q2 = (act) ? n2 : q2;                                     \
        q3 = (act) ? n3 : q3;                                     \
    }

    // prologue: chunks 0 and 1 in flight
    ISSUE_CHUNK(0);
    ISSUE_CHUNK(1);

    int m = 1, k = 0;
    while (m + 31 <= last) {
        asm volatile("cp.async.wait_group 1;");   // chunk k landed
        const float* sb = SE + (k & 1) * 4096 + lane * 4;   // this lane's slot
        // depth-2 e prefetch
        float4 e0 = *(const float4*)(sb);
        float4 e1 = *(const float4*)(sb + 128);
#pragma unroll
        for (int s = 0; s < 32; s++) {
            float4 e = e0;
            e0 = e1;
            if (s < 30) e1 = *(const float4*)(sb + (s + 2) * 128);
            STEPQ_H(e);
            if (s == 15) RESCALE_R();
        }
        ISSUE_CHUNK(k + 2);                       // refill freed buffer (k&1)
        RESCALE_R();
        m += 32; k++;
    }

    // tail: <=31 steps, all rows already in buffer k&1
    asm volatile("cp.async.wait_group 0;");
    {
        const float* sb = SE + (k & 1) * 4096 + lane * 4;
#pragma unroll
        for (int s = 0; s < 32; s++) {
            float4 e = *(const float4*)(sb + s * 128);
            STEPQ_PRED(e, (m + s) <= last);
        }
    }

#undef ISSUE_CHUNK
#undef STEPQ_H
#undef RESCALE_R
#undef STEPQ_PRED

    // extract alpha_last, fold loss reduction (proven ticket scheme)
    {
        const int idx = txt_len - 1;
        const int sel = idx & 3;
        float v = (sel == 0) ? q0 : (sel == 1) ? q1 : (sel == 2) ? q2 : q3;
        v = __shfl_sync(0xffffffffu, v, idx >> 2);
        if (lane == 0) {
            float alpha = __logf(v) + (float)kTot * 0.69314718055994531f + L0;
            g_alpha[b] = alpha / (float)mel_len;
            __threadfence();
            unsigned ticket = atomicAdd(&g_cnt, 1u);
            if (ticket == BB - 1) {
                __threadfence();
                float s = 0.f;
#pragma unroll
                for (int i = 0; i < BB; i++)
                    s += ((volatile float*)g_alpha)[i];
                ((float*)out_base)[0] = -s * (1.f / BB);
                g_cnt = 0;   // reset for next graph replay
            }
        }
    }
}

// ---------------------------------------------------------------------------
extern "C" void kernel_launch(void* const* d_in, const int* in_sizes, int n_in,
                              void* d_out, int out_size)
{
    const float* ml  = (const float*)d_in[0];   // mu_logvar [16,128,160]
    const float* mel = (const float*)d_in[1];   // melspec   [16,80,512]
    const int*   tl  = (const int*)d_in[2];     // text_lengths [16]
    const int*   mll = (const int*)d_in[3];     // mel_lengths  [16]
    float* out = (float*)d_out;                 // [0]=loss, [1..]=log_prob_matrix

    cudaFuncSetAttribute(k_logprob,
                         cudaFuncAttributeMaxDynamicSharedMemorySize, SM_TOTAL);

    k_logprob<<<dim3(MM / MBLK, TT / TBLK, BB), K1_THREADS, SM_TOTAL>>>(
        ml, mel, out + 1);
    k_scan<<<BB, 32>>>(out, tl, mll);
}

// round 13
// speedup vs baseline: 1.6217x; 1.0779x over previous
#include <cuda_runtime.h>
#include <cuda_bf16.h>
#include <cstdint>

// Problem constants (fixed by the dataset)
#define BB  16
#define TT  128   // txt_T
#define MM  512   // mel_T
#define NC  80    // N_MEL

// k_logprob tiling (round-4 shape, x^2 now computed on the fly)
#define TBLK 32
#define MBLK 128
#define K1_THREADS 128

// Scratch (no cudaMalloc allowed).
__device__ __align__(16) float g_elp[(size_t)BB * MM * TT + 4096]; // exp(lp), [b][m][t]
__device__ float g_alpha[BB];
__device__ unsigned g_cnt = 0;

// smem layout (bytes) for k_logprob — X tile only (62 KB -> 3 blocks/SM)
#define SM_X_OFF  0                             // u64 [NC][64] = 40960
#define SM_WA_OFF (NC * 64 * 8)                 // float2[32][80] = 20480
#define SM_KP_OFF (SM_WA_OFF + TBLK * NC * 8)   // 61440
#define SM_KC_OFF (SM_KP_OFF + TBLK * 4 * 4)    // 61952
#define SM_TOTAL  (SM_KC_OFF + TBLK * 4)        // 62080

// ---- packed f32x2 helpers (sm_103a dual-fp32 pipe; PTX-only) ----
__device__ __forceinline__ void fma2(unsigned long long& d,
                                     unsigned long long a,
                                     unsigned long long b) {
    asm("fma.rn.f32x2 %0, %1, %2, %0;" : "+l"(d) : "l"(a), "l"(b));
}
__device__ __forceinline__ unsigned long long mul2(unsigned long long a,
                                                   unsigned long long b) {
    unsigned long long d;
    asm("mul.rn.f32x2 %0, %1, %2;" : "=l"(d) : "l"(a), "l"(b));
    return d;
}
__device__ __forceinline__ unsigned long long pack2(float lo, float hi) {
    unsigned long long r;
    asm("mov.b64 %0, {%1, %2};" : "=l"(r) : "f"(lo), "f"(hi));
    return r;
}
__device__ __forceinline__ float2 unpack2(unsigned long long v) {
    float lo, hi;
    asm("mov.b64 {%0, %1}, %2;" : "=f"(lo), "=f"(hi) : "l"(v));
    return make_float2(lo, hi);
}

// ---------------------------------------------------------------------------
// Kernel 1: log_prob_matrix + exp(log_prob) scratch. Round-4 structure;
// ONE change: the x^2 smem tile is gone — squares computed per-thread with
// independent mul.rn.f32x2 (no dependency chain, unlike R8's Horner).
// smem 103KB -> 62KB => 3 blocks/SM (was 2) for latency hiding.
// ---------------------------------------------------------------------------
__global__ __launch_bounds__(K1_THREADS)
void k_logprob(const float* __restrict__ ml,     // [B, TT, 2*NC]
               const float* __restrict__ mel,    // [B, NC, MM]
               float* __restrict__ lpm)          // [B, TT, MM] (d_out + 1)
{
    extern __shared__ char sm[];
    unsigned long long* Xs = (unsigned long long*)(sm + SM_X_OFF);  // [NC][64]
    float2* wa = (float2*)(sm + SM_WA_OFF);  // [TBLK][NC] = {w, a}
    float*  kp = (float*) (sm + SM_KP_OFF);  // [TBLK][4]
    float*  kc = (float*) (sm + SM_KC_OFF);  // [TBLK]

    const int b   = blockIdx.z;
    const int t0  = blockIdx.y * TBLK;
    const int m0  = blockIdx.x * MBLK;
    const int tid = threadIdx.x;

    // Phase A: per-t coefficients. thread -> (t = tid/4, c-lane = tid%4)
    {
        const int t  = tid >> 2;
        const int cl = tid & 3;
        const float* row = ml + ((size_t)(b * TT + t0 + t)) * (2 * NC);
        float kpart = 0.f;
#pragma unroll
        for (int i = 0; i < 20; i++) {
            int c = cl + 4 * i;
            float mu = row[c];
            float lv = row[NC + c];
            float w  = __expf(-lv);
            float a  = -2.f * w * mu;
            wa[t * NC + c] = make_float2(w, a);
            kpart += __fmaf_rn(w * mu, mu, lv);
        }
        kp[t * 4 + cl] = kpart;
    }

    // Phase B: melspec tile -> packed x pairs (x only; x^2 computed in-loop)
    for (int lin = tid; lin < NC * 64; lin += K1_THREADS) {
        int c = lin >> 6;
        int p = lin & 63;
        float2 x = ((const float2*)(mel + ((size_t)(b * NC + c)) * MM + m0))[p];
        Xs[c * 64 + p] = pack2(x.x, x.y);
    }
    __syncthreads();

    if (tid < TBLK) {
        kc[tid] = kp[tid*4] + kp[tid*4+1] + kp[tid*4+2] + kp[tid*4+3];
    }
    __syncthreads();

    // Phase C: FFMA2 micro-tile 4t x 4 m-pairs (x^2 via independent MUL2)
    const int tx = tid & 15;     // m-pair lane
    const int ty = tid >> 4;     // t group (4 consecutive t)
    unsigned long long acc[4][4];
#pragma unroll
    for (int tt = 0; tt < 4; tt++)
#pragma unroll
        for (int j = 0; j < 4; j++) acc[tt][j] = 0ull;

#pragma unroll 2
    for (int c = 0; c < NC; c++) {
        unsigned long long x2p[4], xp[4];
#pragma unroll
        for (int j = 0; j < 4; j++) {
            xp[j]  = Xs[c * 64 + tx + 16 * j];
            x2p[j] = mul2(xp[j], xp[j]);
        }
#pragma unroll
        for (int tt = 0; tt < 4; tt++) {
            float2 wv = wa[(4 * ty + tt) * NC + c];
            unsigned long long ww = pack2(wv.x, wv.x);
            unsigned long long aa = pack2(wv.y, wv.y);
#pragma unroll
            for (int j = 0; j < 4; j++) {
                fma2(acc[tt][j], ww, x2p[j]);
                fma2(acc[tt][j], aa, xp[j]);
            }
        }
    }

    // Epilogue
    const float inv = -1.f / (2.f * NC);
    float kt[4];
#pragma unroll
    for (int tt = 0; tt < 4; tt++) kt[tt] = kc[4 * ty + tt];
    const int tg = t0 + 4 * ty;

#pragma unroll
    for (int j = 0; j < 4; j++) {
        const int me = m0 + 2 * (tx + 16 * j);   // even m
        float e0[4], e1[4];
#pragma unroll
        for (int tt = 0; tt < 4; tt++) {
            float2 v = unpack2(acc[tt][j]);
            float lp0 = (v.x + kt[tt]) * inv;
            float lp1 = (v.y + kt[tt]) * inv;
            float* dst = lpm + ((size_t)(b * TT + tg + tt)) * MM + me;
            dst[0] = lp0;          // d_out+1 is only 4B aligned: scalar stores
            dst[1] = lp1;
            e0[tt] = __expf(lp0);
            e1[tt] = __expf(lp1);
        }
        *(float4*)(g_elp + ((size_t)b * MM + me)     * TT + tg) =
            make_float4(e0[0], e0[1], e0[2], e0[3]);
        *(float4*)(g_elp + ((size_t)b * MM + me + 1) * TT + tg) =
            make_float4(e1[0], e1[1], e1[2], e1[3]);
    }
}

// ---------------------------------------------------------------------------
// Kernel 2: probability-domain serial scan. EXACT round-12 version (WIN):
// E ring in shared memory fed by cp.async, 2x32-row buffers, depth-2 register
// e-prefetch, hoisted shfl, redux rescale every 16 steps, select-freeze tail,
// fused ticket loss reduction.
// ---------------------------------------------------------------------------
__global__ __launch_bounds__(32)
void k_scan(const float* __restrict__ out_base,  // d_out (out[0]=loss, +1=lpm)
            const int* __restrict__ tlen,
            const int* __restrict__ mlen)
{
    __shared__ __align__(16) float SE[64 * 128];  // 2 buffers x 32 rows x 128 t

    const int b    = blockIdx.x;
    const int lane = threadIdx.x;
    const float* Eb = g_elp + (size_t)b * MM * TT;   // [m][128]

    const int mel_len = mlen[b];
    const int txt_len = tlen[b];
    const int last    = mel_len - 1;          // >= 255 for this dataset

    float q0 = (lane == 0) ? 1.f : 0.f;
    float q1 = 0.f, q2 = 0.f, q3 = 0.f;
    float top = 0.f;
    const bool isL0 = (lane == 0);
    const float L0 = out_base[1 + (size_t)b * TT * MM];  // lp[b,0,0]
    int kTot = 0;

    const uint32_t se_base =
        (uint32_t)__cvta_generic_to_shared(SE) + lane * 16;

#define ISSUE_CHUNK(kk)                                               \
    {                                                                 \
        uint32_t d0 = se_base + ((kk) & 1) * 16384;                   \
        _Pragma("unroll")                                             \
        for (int s = 0; s < 32; s++) {                                \
            int row = 1 + 32 * (kk) + s;                              \
            if (row > MM - 1) row = MM - 1;                           \
            const float* src = Eb + (size_t)row * TT + lane * 4;      \
            asm volatile("cp.async.cg.shared.global [%0], [%1], 16;"  \
                         :: "r"(d0 + s * 512), "l"(src));             \
        }                                                             \
        asm volatile("cp.async.commit_group;");                       \
    }

#define STEPQ_H(e)                                                \
    {                                                             \
        float n3 = (q3 + q2) * (e).w;                             \
        float tn = __shfl_up_sync(0xffffffffu, n3, 1);            \
        float n2 = (q2 + q1) * (e).z;                             \
        float n1 = (q1 + q0) * (e).y;                             \
        float n0 = (q0 + top) * (e).x;                            \
        top = isL0 ? 0.f : tn;                                    \
        q0 = n0; q1 = n1; q2 = n2; q3 = n3;                       \
    }

#define RESCALE_R()                                               \
    {                                                             \
        float mxq = fmaxf(fmaxf(q0, q1), fmaxf(q2, q3));          \
        unsigned mb;                                              \
        asm("redux.sync.max.u32 %0, %1, 0xffffffff;"              \
            : "=r"(mb) : "r"(__float_as_uint(mxq)));              \
        if (mb != 0u) {                                           \
            int eb = (int)(mb >> 23) & 0xff;                      \
            float sc = __int_as_float((254 - eb) << 23);          \
            q0 *= sc; q1 *= sc; q2 *= sc; q3 *= sc;               \
            top *= sc;                                            \
            kTot += eb - 127;                                     \
        }                                                         \
    }

#define STEPQ_PRED(e, act)                                        \
    {                                                             \
        float tp = __shfl_up_sync(0xffffffffu, q3, 1);            \
        if (isL0) tp = 0.f;                                       \
        float n0 = (q0 + tp) * (e).x;                             \
        float n1 = (q1 + q0) * (e).y;                             \
        float n2 = (q2 + q1) * (e).z;                             \
        float n3 = (q3 + q2) * (e).w;                             \
        q0 = (act) ? n0 : q0;                                     \
        q1 = (act) ? n1 : q1;                                     \
        q2 = (act) ? n2 : q2;                                     \
        q3 = (act) ? n3 : q3;                                     \
    }

    ISSUE_CHUNK(0);
    ISSUE_CHUNK(1);

    int m = 1, k = 0;
    while (m + 31 <= last) {
        asm volatile("cp.async.wait_group 1;");   // chunk k landed
        const float* sb = SE + (k & 1) * 4096 + lane * 4;
        float4 e0 = *(const float4*)(sb);
        float4 e1 = *(const float4*)(sb + 128);
#pragma unroll
        for (int s = 0; s < 32; s++) {
            float4 e = e0;
            e0 = e1;
            if (s < 30) e1 = *(const float4*)(sb + (s + 2) * 128);
            STEPQ_H(e);
            if (s == 15) RESCALE_R();
        }
        ISSUE_CHUNK(k + 2);
        RESCALE_R();
        m += 32; k++;
    }

    asm volatile("cp.async.wait_group 0;");
    {
        const float* sb = SE + (k & 1) * 4096 + lane * 4;
#pragma unroll
        for (int s = 0; s < 32; s++) {
            float4 e = *(const float4*)(sb + s * 128);
            STEPQ_PRED(e, (m + s) <= last);
        }
    }

#undef ISSUE_CHUNK
#undef STEPQ_H
#undef RESCALE_R
#undef STEPQ_PRED

    {
        const int idx = txt_len - 1;
        const int sel = idx & 3;
        float v = (sel == 0) ? q0 : (sel == 1) ? q1 : (sel == 2) ? q2 : q3;
        v = __shfl_sync(0xffffffffu, v, idx >> 2);
        if (lane == 0) {
            float alpha = __logf(v) + (float)kTot * 0.69314718055994531f + L0;
            g_alpha[b] = alpha / (float)mel_len;
            __threadfence();
            unsigned ticket = atomicAdd(&g_cnt, 1u);
            if (ticket == BB - 1) {
                __threadfence();
                float s = 0.f;
#pragma unroll
                for (int i = 0; i < BB; i++)
                    s += ((volatile float*)g_alpha)[i];
                ((float*)out_base)[0] = -s * (1.f / BB);
                g_cnt = 0;   // reset for next graph replay
            }
        }
    }
}

// ---------------------------------------------------------------------------
extern "C" void kernel_launch(void* const* d_in, const int* in_sizes, int n_in,
                              void* d_out, int out_size)
{
    const float* ml  = (const float*)d_in[0];   // mu_logvar [16,128,160]
    const float* mel = (const float*)d_in[1];   // melspec   [16,80,512]
    const int*   tl  = (const int*)d_in[2];     // text_lengths [16]
    const int*   mll = (const int*)d_in[3];     // mel_lengths  [16]
    float* out = (float*)d_out;                 // [0]=loss, [1..]=log_prob_matrix

    cudaFuncSetAttribute(k_logprob,
                         cudaFuncAttributeMaxDynamicSharedMemorySize, SM_TOTAL);

    k_logprob<<<dim3(MM / MBLK, TT / TBLK, BB), K1_THREADS, SM_TOTAL>>>(
        ml, mel, out + 1);
    k_scan<<<BB, 32>>>(out, tl, mll);
}